// round 2
// baseline (speedup 1.0000x reference)
#include <cuda_runtime.h>
#include <string.h>

#define B_TOT   4096
#define T_TOT   512
#define NF      16
#define NG      12      // 3 gates * H(=4)
#define BPB     32      // batches per block
#define CH      4       // timesteps per chunk
#define NCHUNK  (T_TOT / CH)   // 128

// ---------- packed f32x2 helpers (sm_103a FFMA2 path) ----------
union F2U { float2 f; unsigned long long u; };

__device__ __forceinline__ float2 fma2(float2 a, float2 b, float2 c) {
    F2U A, B, C, D; A.f = a; B.f = b; C.f = c;
    asm("fma.rn.f32x2 %0, %1, %2, %3;" : "=l"(D.u) : "l"(A.u), "l"(B.u), "l"(C.u));
    return D.f;
}
__device__ __forceinline__ float2 add2(float2 a, float2 b) {
    F2U A, B, D; A.f = a; B.f = b;
    asm("add.rn.f32x2 %0, %1, %2;" : "=l"(D.u) : "l"(A.u), "l"(B.u));
    return D.f;
}
__device__ __forceinline__ float2 mul2(float2 a, float2 b) {
    F2U A, B, D; A.f = a; B.f = b;
    asm("mul.rn.f32x2 %0, %1, %2;" : "=l"(D.u) : "l"(A.u), "l"(B.u));
    return D.f;
}

__global__ void __launch_bounds__(256, 1)
gru_fused_kernel(const float* __restrict__ x,
                 const float* __restrict__ w_ih,
                 const float* __restrict__ w_hh,
                 const float* __restrict__ b_ih,
                 const float* __restrict__ b_hh,
                 const float* __restrict__ fc_w,
                 const float* __restrict__ fc_b,
                 float* __restrict__ out)
{
    // gi tiles: [buf][ (t*BPB + b) * NG + g ]
    __shared__ __align__(16) float gibuf[2][CH * BPB * NG];   // 12288 B

    const int tid = threadIdx.x;
    const int b0  = blockIdx.x * BPB;

    // ---------------- producer identity (ALL 256 threads produce) ----------------
    // 128 cells per chunk (32 batches x 4 timesteps), 2 threads per cell
    // (gate-halves 0..5 / 6..11).
    const int cell = tid & 127;
    const int half = tid >> 7;
    const int pb = cell >> 2;          // batch within block
    const int pt = cell & 3;           // timestep within chunk
    const int g0 = half * 6;           // first gate of this thread's half

    // w_ih half in registers, packed over feature pairs: wp[g][k] = (w[g0+g][2k], w[g0+g][2k+1])
    float2 wp[6][8];
    float  bi[6];
    #pragma unroll
    for (int g = 0; g < 6; ++g) {
        const float* wr = w_ih + (g0 + g) * NF;
        #pragma unroll
        for (int q = 0; q < 4; ++q) {
            float4 v = *(const float4*)(wr + q * 4);
            wp[g][2*q]     = make_float2(v.x, v.y);
            wp[g][2*q + 1] = make_float2(v.z, v.w);
        }
        bi[g] = b_ih[g0 + g];
    }

    // ---------------- consumer identity (warps 4..7, one per SMSP) ----------------
    const int wid  = tid >> 5;
    const int lane = tid & 31;
    const bool is_cons = (wid >= 4);
    const int cj = lane & 3;                       // h-unit owned by this lane
    const int cb = (wid - 4) * 8 + (lane >> 2);    // batch within block (0..31)

    // per-lane permuted recurrent weights: index m refers to h_{cj^m}
    float2 wrz[4] = {};      // (w_r[cj][cj^m], w_z[cj][cj^m])
    float  wn[4]  = {};      // w_n[cj][cj^m]
    float2 bhrz   = make_float2(0.f, 0.f);
    float  bhn = 0.f, fw0 = 0.f, fw1 = 0.f, fw2 = 0.f, fw3 = 0.f, fb = 0.f;
    if (is_cons) {
        #pragma unroll
        for (int m = 0; m < 4; ++m) {
            int k = cj ^ m;
            wrz[m] = make_float2(w_hh[cj * 4 + k], w_hh[(4 + cj) * 4 + k]);
            wn[m]  = w_hh[(8 + cj) * 4 + k];
        }
        bhrz = make_float2(b_hh[cj], b_hh[4 + cj]);
        bhn  = b_hh[8 + cj];
        fw0 = fc_w[0]; fw1 = fc_w[1]; fw2 = fc_w[2]; fw3 = fc_w[3];
        fb  = fc_b[0];
    }
    // h state in "relative" order: r0=h_{cj}, r1=h_{cj^1}, r2=h_{cj^2}, r3=h_{cj^3}
    float r0 = 0.f, r1 = 0.f, r2 = 0.f, r3 = 0.f;

    // ---------------- x double-buffer in registers ----------------
    const float* xbase = x + ((size_t)(b0 + pb) * T_TOT + pt) * NF;
    float2 xc[8], xn[8];
    {   // prologue: chunk 0
        const float4* p = (const float4*)xbase;
        #pragma unroll
        for (int q = 0; q < 4; ++q) {
            float4 v = p[q];
            xc[2*q]   = make_float2(v.x, v.y);
            xc[2*q+1] = make_float2(v.z, v.w);
        }
    }

    for (int it = 0; it <= NCHUNK; ++it) {
        // ---- prefetch x for chunk it+1 (latency hidden across the interval) ----
        if (it < NCHUNK - 1) {
            const float4* p = (const float4*)(xbase + (size_t)(it + 1) * CH * NF);
            #pragma unroll
            for (int q = 0; q < 4; ++q) {
                float4 v = p[q];
                xn[2*q]   = make_float2(v.x, v.y);
                xn[2*q+1] = make_float2(v.z, v.w);
            }
        }

        // ---- produce gi for chunk it (packed f32x2 GEMV) ----
        if (it < NCHUNK) {
            float2 acc[6];
            #pragma unroll
            for (int g = 0; g < 6; ++g) acc[g] = make_float2(bi[g], 0.f);
            #pragma unroll
            for (int k = 0; k < 8; ++k) {
                #pragma unroll
                for (int g = 0; g < 6; ++g) acc[g] = fma2(xc[k], wp[g][k], acc[g]);
            }
            float* gw = &gibuf[it & 1][(pt * BPB + pb) * NG + g0];
            *(float2*)(gw + 0) = make_float2(acc[0].x + acc[0].y, acc[1].x + acc[1].y);
            *(float2*)(gw + 2) = make_float2(acc[2].x + acc[2].y, acc[3].x + acc[3].y);
            *(float2*)(gw + 4) = make_float2(acc[4].x + acc[4].y, acc[5].x + acc[5].y);
        }

        // ---- consume chunk it-1 : 4 GRU steps ----
        if (is_cons && it >= 1) {
            const float* gb = gibuf[(it - 1) & 1];
            #pragma unroll
            for (int s = 0; s < CH; ++s) {
                const float* g = gb + (s * BPB + cb) * NG;
                float gir = g[cj], giz = g[4 + cj], gin = g[8 + cj];

                // gh_r / gh_z packed GEMV
                float2 arg = add2(make_float2(gir, giz), bhrz);
                arg = fma2(make_float2(r0, r0), wrz[0], arg);
                arg = fma2(make_float2(r1, r1), wrz[1], arg);
                arg = fma2(make_float2(r2, r2), wrz[2], arg);
                arg = fma2(make_float2(r3, r3), wrz[3], arg);
                // gh_n scalar GEMV
                float ghn = fmaf(r3, wn[3], fmaf(r2, wn[2], fmaf(r1, wn[1], fmaf(r0, wn[0], bhn))));

                // sigmoid(a) = 0.5 + (a/4) * N(u)/D(u), u=(a/2)^2  [Pade 5/4 tanh, rel err < 1e-5]
                float2 y  = mul2(arg, make_float2(0.5f, 0.5f));
                float2 u  = mul2(y, y);
                float2 t  = add2(u, make_float2(105.f, 105.f));
                float2 num = fma2(u, t, make_float2(945.f, 945.f));
                float2 den = fma2(u, make_float2(15.f, 15.f), make_float2(420.f, 420.f));
                den = fma2(u, den, make_float2(945.f, 945.f));
                float2 yh = mul2(y, make_float2(0.5f, 0.5f));
                float rg = fmaf(yh.x, __fdividef(num.x, den.x), 0.5f);
                float zg = fmaf(yh.y, __fdividef(num.y, den.y), 0.5f);

                // n = tanh(gi_n + r*gh_n), same Pade
                float na   = fmaf(rg, ghn, gin);
                float un   = na * na;
                float nnum = fmaf(un, un + 105.f, 945.f);
                float nden = fmaf(un, fmaf(un, 15.f, 420.f), 945.f);
                float ng   = na * __fdividef(nnum, nden);

                // exchange: all shfls independent (no dependent shfl chain)
                float z3 = __shfl_xor_sync(0xffffffffu, zg, 3);
                float n3 = __shfl_xor_sync(0xffffffffu, ng, 3);
                float hj = fmaf(zg, r0 - ng, ng);        // h'_{cj}
                float h3 = fmaf(z3, r3 - n3, n3);        // h'_{cj^3} computed locally
                float h1 = __shfl_xor_sync(0xffffffffu, hj, 1);
                float h2 = __shfl_xor_sync(0xffffffffu, hj, 2);
                r0 = hj; r1 = h1; r2 = h2; r3 = h3;
            }
        }

        __syncthreads();

        if (it < NCHUNK - 1) {
            #pragma unroll
            for (int k = 0; k < 8; ++k) xc[k] = xn[k];
        }
    }

    // final FC: lane with cj==0 holds (h0,h1,h2,h3) in order
    if (is_cons && cj == 0) {
        out[b0 + cb] = fmaf(r3, fw3, fmaf(r2, fw2, fmaf(r1, fw1, fmaf(r0, fw0, fb))));
    }
}

extern "C" void kernel_launch(void* const* d_in, const int* in_sizes, int n_in,
                              void* d_out, int out_size)
{
    const float* x    = (const float*)d_in[0];
    const float* w_ih = (const float*)d_in[1];
    const float* w_hh = (const float*)d_in[2];
    const float* b_ih = (const float*)d_in[3];
    const float* b_hh = (const float*)d_in[4];
    const float* fc_w = (const float*)d_in[5];
    const float* fc_b = (const float*)d_in[6];
    float* out = (float*)d_out;

    gru_fused_kernel<<<B_TOT / BPB, 256>>>(x, w_ih, w_hh, b_ih, b_hh, fc_w, fc_b, out);
}

// round 3
// speedup vs baseline: 1.3208x; 1.3208x over previous
#include <cuda_runtime.h>

#define B_TOT   4096
#define T_TOT   512
#define NF      16
#define NG      12
#define BPB     32
#define CH      4
#define NCHUNK  (T_TOT / CH)   // 128

using u64 = unsigned long long;

#define PACK2(d, lo, hi) asm("mov.b64 %0, {%1, %2};" : "=l"(d) : "f"(lo), "f"(hi))
#define FMA2(d, a, b, c) asm("fma.rn.f32x2 %0, %1, %2, %3;" : "=l"(d) : "l"(a), "l"(b), "l"(c))

__global__ void __launch_bounds__(256, 1)
gru_fused_kernel(const float* __restrict__ x,
                 const float* __restrict__ w_ih,
                 const float* __restrict__ w_hh,
                 const float* __restrict__ b_ih,
                 const float* __restrict__ b_hh,
                 const float* __restrict__ fc_w,
                 const float* __restrict__ fc_b,
                 float* __restrict__ out)
{
    // gi tiles: [buf][ (t*BPB + b) * NG + g ]   (12 KB)
    __shared__ __align__(16) float gibuf[2][CH * BPB * NG];

    const int tid  = threadIdx.x;
    const int b0   = blockIdx.x * BPB;
    const int wid  = tid >> 5;
    const int lane = tid & 31;

    if (tid < 128) {
        // =========== PRODUCERS (warps 0-3) ===========
        // 128 cells/chunk x 2 gate-halves = 256 tasks; 128 threads x 2 tasks.
        // thread handles cells {idx, idx+64} for gate half `half`.
        const int half = tid >> 6;          // 0: gates 0-5, 1: gates 6-11
        const int idx  = tid & 63;          // cell A
        const int g0   = half * 6;
        const int pbA  = idx >> 2;          // batch of cell A
        const int ptA  = idx & 3;           // timestep-in-chunk

        // weights packed over adjacent gate pairs: wq[p][k] = (w[g0+2p][k], w[g0+2p+1][k])
        u64 wq[3][NF];
        u64 bq[3];
        #pragma unroll
        for (int p = 0; p < 3; ++p) {
            const float* r0 = w_ih + (g0 + 2 * p) * NF;
            const float* r1 = r0 + NF;
            #pragma unroll
            for (int k = 0; k < NF; ++k) PACK2(wq[p][k], r0[k], r1[k]);
            PACK2(bq[p], b_ih[g0 + 2 * p], b_ih[g0 + 2 * p + 1]);
        }

        const float* xA = x + ((size_t)(b0 + pbA) * T_TOT + ptA) * NF;
        const float* xB = xA + (size_t)16 * T_TOT * NF;   // cell B = batch pbA+16

        // register double buffer: 2 cells x 16 floats, current + next
        float4 xc[2][4], xn[2][4];
        #pragma unroll
        for (int q = 0; q < 4; ++q) {
            xc[0][q] = ((const float4*)xA)[q];
            xc[1][q] = ((const float4*)xB)[q];
        }

        for (int it = 0; it <= NCHUNK; ++it) {
            if (it < NCHUNK - 1) {
                const float4* pA = (const float4*)(xA + (size_t)(it + 1) * CH * NF);
                const float4* pB = (const float4*)(xB + (size_t)(it + 1) * CH * NF);
                #pragma unroll
                for (int q = 0; q < 4; ++q) { xn[0][q] = pA[q]; xn[1][q] = pB[q]; }
            }

            if (it < NCHUNK) {
                float* gbase = gibuf[it & 1];
                #pragma unroll
                for (int c = 0; c < 2; ++c) {
                    const float* xv = (const float*)xc[c];
                    u64 a0 = bq[0], a1 = bq[1], a2 = bq[2];
                    #pragma unroll
                    for (int k = 0; k < NF; ++k) {
                        u64 xb; PACK2(xb, xv[k], xv[k]);
                        FMA2(a0, xb, wq[0][k], a0);
                        FMA2(a1, xb, wq[1][k], a1);
                        FMA2(a2, xb, wq[2][k], a2);
                    }
                    int cell = idx + c * 64;
                    int off  = ((ptA * BPB) + (pbA + c * 16)) * NG + g0;
                    (void)cell;
                    u64* gw = (u64*)(gbase + off);
                    gw[0] = a0; gw[1] = a1; gw[2] = a2;   // (g,g+1) pairs, 8B aligned
                }
            }

            __syncthreads();

            if (it < NCHUNK - 1) {
                #pragma unroll
                for (int q = 0; q < 4; ++q) { xc[0][q] = xn[0][q]; xc[1][q] = xn[1][q]; }
            }
        }
    } else {
        // =========== CONSUMERS (warps 4-7, one per SMSP) ===========
        // 8 batches per warp, 4 lanes per batch; lane owns gate-unit m,
        // holds FULL h[0..3] in canonical order (no permutation).
        const int m  = lane & 3;
        const int cb = (wid - 4) * 8 + (lane >> 2);   // batch within block

        float whr[4], whz[4], whn[4];
        #pragma unroll
        for (int k = 0; k < 4; ++k) {
            whr[k] = w_hh[m * 4 + k];
            whz[k] = w_hh[(4 + m) * 4 + k];
            whn[k] = w_hh[(8 + m) * 4 + k];
        }
        const float bhr = b_hh[m], bhz = b_hh[4 + m], bhn = b_hh[8 + m];
        const float fw0 = fc_w[0], fw1 = fc_w[1], fw2 = fc_w[2], fw3 = fc_w[3];
        const float fb  = fc_b[0];

        float h[4] = {0.f, 0.f, 0.f, 0.f};
        const int src = (lane & 0x1c);   // base lane of this batch's quad

        for (int it = 0; it <= NCHUNK; ++it) {
            if (it >= 1) {
                const float* gb = gibuf[(it - 1) & 1];
                // hoist all 12 independent LDS for the chunk
                float gr[CH], gz[CH], gn[CH];
                #pragma unroll
                for (int s = 0; s < CH; ++s) {
                    const float* g = gb + (s * BPB + cb) * NG;
                    gr[s] = g[m]; gz[s] = g[4 + m]; gn[s] = g[8 + m];
                }
                #pragma unroll
                for (int s = 0; s < CH; ++s) {
                    float ghr = fmaf(whr[3], h[3], fmaf(whr[2], h[2],
                                fmaf(whr[1], h[1], fmaf(whr[0], h[0], bhr))));
                    float ghz = fmaf(whz[3], h[3], fmaf(whz[2], h[2],
                                fmaf(whz[1], h[1], fmaf(whz[0], h[0], bhz))));
                    float ghn = fmaf(whn[3], h[3], fmaf(whn[2], h[2],
                                fmaf(whn[1], h[1], fmaf(whn[0], h[0], bhn))));
                    float ar = gr[s] + ghr;
                    float az = gz[s] + ghz;

                    // sigmoid(a) = 0.5 + (a/4)*(15+u)/(15+6u), u=(a/2)^2  (|a|<=1.2)
                    float tr = ar * ar, ur = tr * 0.25f;
                    float qr = __fdividef(ur + 15.f, fmaf(ur, 6.f, 15.f));
                    float rg = fmaf(ar * 0.25f, qr, 0.5f);

                    float tz = az * az, uz = tz * 0.25f;
                    float qz = __fdividef(uz + 15.f, fmaf(uz, 6.f, 15.f));
                    float zg = fmaf(az * 0.25f, qz, 0.5f);

                    // n = tanh(gi_n + r*gh_n), Pade[5,4]
                    float na   = fmaf(rg, ghn, gn[s]);
                    float un   = na * na;
                    float nnum = fmaf(un, un + 105.f, 945.f);
                    float nden = fmaf(un, fmaf(un, 15.f, 420.f), 945.f);
                    float ng   = na * __fdividef(nnum, nden);

                    float hm = fmaf(zg, h[m] - ng, ng);

                    // one level of 4 INDEPENDENT index-shuffles
                    h[0] = __shfl_sync(0xffffffffu, hm, src | 0);
                    h[1] = __shfl_sync(0xffffffffu, hm, src | 1);
                    h[2] = __shfl_sync(0xffffffffu, hm, src | 2);
                    h[3] = __shfl_sync(0xffffffffu, hm, src | 3);
                }
            }
            __syncthreads();
        }

        if (m == 0) {
            out[b0 + cb] = fmaf(h[3], fw3, fmaf(h[2], fw2,
                           fmaf(h[1], fw1, fmaf(h[0], fw0, fb))));
        }
    }
}

extern "C" void kernel_launch(void* const* d_in, const int* in_sizes, int n_in,
                              void* d_out, int out_size)
{
    const float* x    = (const float*)d_in[0];
    const float* w_ih = (const float*)d_in[1];
    const float* w_hh = (const float*)d_in[2];
    const float* b_ih = (const float*)d_in[3];
    const float* b_hh = (const float*)d_in[4];
    const float* fc_w = (const float*)d_in[5];
    const float* fc_b = (const float*)d_in[6];
    float* out = (float*)d_out;

    gru_fused_kernel<<<B_TOT / BPB, 256>>>(x, w_ih, w_hh, b_ih, b_hh, fc_w, fc_b, out);
}